// round 4
// baseline (speedup 1.0000x reference)
#include <cuda_runtime.h>
#include <cstdint>

// Problem constants
#define T_DIM 2048
#define B_DIM 16
#define D_DIM 1024

#define NC      128         // persistent CTAs (all co-resident; 128 < 148 SMs)
#define NC_HALF 64          // CTAs per independent batch-group barrier

typedef unsigned long long ull;

// ---------------------------------------------------------------------------
// Packed fp32x2 helpers (sm_100+; IEEE-identical per lane to scalar FFMA)
// ---------------------------------------------------------------------------
__device__ __forceinline__ ull fma2(ull a, ull b, ull c) {
    ull d;
    asm("fma.rn.f32x2 %0, %1, %2, %3;" : "=l"(d) : "l"(a), "l"(b), "l"(c));
    return d;
}
__device__ __forceinline__ ull pack2(float lo, float hi) {
    ull d;
    asm("mov.b64 %0, {%1, %2};" : "=l"(d) : "f"(lo), "f"(hi));
    return d;
}
__device__ __forceinline__ void unpack2(ull v, float& lo, float& hi) {
    asm("mov.b64 {%0, %1}, %2;" : "=f"(lo), "=f"(hi) : "l"(v));
}

// ---------------------------------------------------------------------------
// Device-global scratch (allocation-free rule: static __device__ arrays only)
// 16B/256B alignment is load-bearing: float4 / 128-bit accesses trap if
// misaligned (sm_103a wide-operand rule).
// ---------------------------------------------------------------------------
__device__ __align__(256) float g_wx[(size_t)T_DIM * B_DIM * D_DIM];  // x@W_x^T + b
__device__ unsigned g_bar_count[2];   // one barrier per batch group
__device__ unsigned g_bar_gen[2];

// ---------------------------------------------------------------------------
// Software grid barrier over the NC_HALF CTAs of one batch group. Waiters
// poll g_bar_gen with volatile loads (L2 read path, no per-address
// atomic-ALU serialization). count returns to 0 after every use; gen is
// monotonic and compared relatively -> graph-replay clean.
// ---------------------------------------------------------------------------
__device__ __forceinline__ void grid_barrier_half(int grp) {
    __syncthreads();
    if (threadIdx.x == 0) {
        __threadfence();                                        // publish h writes
        unsigned gen  = *(volatile unsigned*)&g_bar_gen[grp];   // stable: release needs OUR count
        unsigned prev = atomicAdd(&g_bar_count[grp], 1u);
        if (prev == NC_HALF - 1) {
            atomicExch(&g_bar_count[grp], 0u);                  // reset BEFORE release
            __threadfence();
            atomicAdd(&g_bar_gen[grp], 1u);                     // release
        } else {
            while (*(volatile unsigned*)&g_bar_gen[grp] == gen) { }
        }
        __threadfence();
    }
    __syncthreads();
}

// ---------------------------------------------------------------------------
// Phase A: Wx[t,b,e] = sum_d x[t,b,d] * W_x[e,d] + bias[e]
// C[M=32768, N=1024] = X * W^T, 128x128 block, 8x8 thread tile, BK=8,
// 256 threads, fp32x2 packed FMA inner loop.
// ---------------------------------------------------------------------------
#define BM 128
#define BN 128
#define BK 8

__global__ void __launch_bounds__(256, 2) gemm_xwx_kernel(
    const float* __restrict__ X, const float* __restrict__ W,
    const float* __restrict__ bias)
{
    __shared__ __align__(16) float As[BK][BM];
    __shared__ __align__(16) float Bs[BK][BN];

    const int bm  = blockIdx.y * BM;
    const int bn  = blockIdx.x * BN;
    const int tid = threadIdx.x;

    const int lrow = tid >> 1;          // 128 rows x 2 threads (8 k each as float4)
    const int lk4  = (tid & 1) * 4;

    const int trow = (tid >> 4) * 8;    // 16x16 thread grid, 8x8 outputs each
    const int tcol = (tid & 15) * 8;

    ull acc2[8][4];                     // [i][j-pair], packed fp32 pairs
#pragma unroll
    for (int i = 0; i < 8; i++)
#pragma unroll
        for (int j = 0; j < 4; j++) acc2[i][j] = 0ull;   // (+0.0f, +0.0f)

    const float* xrow = X + (size_t)(bm + lrow) * D_DIM + lk4;
    const float* wrow = W + (size_t)(bn + lrow) * D_DIM + lk4;

    for (int k0 = 0; k0 < D_DIM; k0 += BK) {
        float4 a4 = *(const float4*)(xrow + k0);
        float4 b4 = *(const float4*)(wrow + k0);
        As[lk4 + 0][lrow] = a4.x; As[lk4 + 1][lrow] = a4.y;
        As[lk4 + 2][lrow] = a4.z; As[lk4 + 3][lrow] = a4.w;
        Bs[lk4 + 0][lrow] = b4.x; Bs[lk4 + 1][lrow] = b4.y;
        Bs[lk4 + 2][lrow] = b4.z; Bs[lk4 + 3][lrow] = b4.w;
        __syncthreads();

#pragma unroll
        for (int k = 0; k < BK; k++) {
            float4 ra0 = *(const float4*)&As[k][trow];
            float4 ra1 = *(const float4*)&As[k][trow + 4];
            // B pairs straight from SMEM as packed fp32x2 (32B-aligned: tcol%8==0)
            ulonglong2 rb01 = *(const ulonglong2*)&Bs[k][tcol];      // (b0,b1),(b2,b3)
            ulonglong2 rb23 = *(const ulonglong2*)&Bs[k][tcol + 4];  // (b4,b5),(b6,b7)
            float ra[8] = {ra0.x, ra0.y, ra0.z, ra0.w, ra1.x, ra1.y, ra1.z, ra1.w};
#pragma unroll
            for (int i = 0; i < 8; i++) {
                ull aa = pack2(ra[i], ra[i]);
                acc2[i][0] = fma2(aa, rb01.x, acc2[i][0]);
                acc2[i][1] = fma2(aa, rb01.y, acc2[i][1]);
                acc2[i][2] = fma2(aa, rb23.x, acc2[i][2]);
                acc2[i][3] = fma2(aa, rb23.y, acc2[i][3]);
            }
        }
        __syncthreads();
    }

    // Epilogue: unpack, add bias, store
#pragma unroll
    for (int i = 0; i < 8; i++) {
        float c[8];
#pragma unroll
        for (int jp = 0; jp < 4; jp++) unpack2(acc2[i][jp], c[2 * jp], c[2 * jp + 1]);
        float* crow = g_wx + (size_t)(bm + trow + i) * D_DIM + bn + tcol;
#pragma unroll
        for (int j = 0; j < 8; j += 4) {
            float4 v;
            v.x = c[j + 0] + bias[bn + tcol + j + 0];
            v.y = c[j + 1] + bias[bn + tcol + j + 1];
            v.z = c[j + 2] + bias[bn + tcol + j + 2];
            v.w = c[j + 3] + bias[bn + tcol + j + 3];
            *(float4*)(crow + j) = v;
        }
    }
}

// ---------------------------------------------------------------------------
// Copy h0 into the h-history buffer at t=0
// ---------------------------------------------------------------------------
__global__ void copy_h0_kernel(const float* __restrict__ h0, float* __restrict__ hbuf)
{
    int i = blockIdx.x * blockDim.x + threadIdx.x;
    if (i < B_DIM * D_DIM) hbuf[i] = h0[i];
}

// ---------------------------------------------------------------------------
// Phase B: persistent scan.
// Grid = 128 CTAs = 2 bgroups (8 batches each) x 64 egroups (16 features).
// The two bgroups are fully independent (each CTA consumes only its own
// bgroup's h slice), so each has its own 64-CTA barrier.
// W_h slice lives in REGISTERS (loaded once): warp w owns k in [w*64,w*64+64),
// lane = e_local*2 + kg -> thread owns (row e0+e_local, 32 k's at kg*32).
// Per step: stage h[t] bgroup slice (32KB) -> SMEM; matvec with 16-way
// e-broadcast LDS reads + packed fp32x2 FMA; pair-shuffle + SMEM cross-warp
// reduce; 128 threads finalize (tanh/silu, h[t+1]+outs stores); half-barrier.
// ---------------------------------------------------------------------------
__global__ void __launch_bounds__(512, 1) scan_kernel(
    const float* __restrict__ Wh, const float* __restrict__ log_alpha_ptr,
    float* __restrict__ outs, float* __restrict__ hbuf)
{
    __shared__ __align__(16) float sh[8 * D_DIM];     // 32 KB: h[t] slice, 8 batches
    __shared__ __align__(16) float red[16][136];      // cross-warp partials (padded)

    const int tid     = threadIdx.x;
    const int w       = tid >> 5;            // warp id: k-range [w*64, w*64+64)
    const int lane    = tid & 31;
    const int e_local = lane >> 1;           // 0..15
    const int kg      = lane & 1;            // k half within warp range
    const int bgroup  = blockIdx.x & 1;      // batches [bgroup*8, bgroup*8+8)
    const int e0      = (blockIdx.x >> 1) * 16;

    // --- W_h slice into registers (once; W never changes across t) ---
    ull wp[16];                               // 8 float4 -> 16 packed pairs
    {
        const float4* wrow = (const float4*)(Wh + (size_t)(e0 + e_local) * D_DIM
                                             + w * 64 + kg * 32);
#pragma unroll
        for (int q = 0; q < 8; q++) {
            float4 v = wrow[q];
            wp[2 * q]     = pack2(v.x, v.y);
            wp[2 * q + 1] = pack2(v.z, v.w);
        }
    }
    const float alpha = expf(log_alpha_ptr[0]);

    // Finalization ids (valid when tid < 128): tid = e*8 + b
    const int    fe   = tid >> 3;
    const int    fb   = tid & 7;
    const size_t fcol = (size_t)(bgroup * 8 + fb) * D_DIM + e0 + fe;

    const int koff = w * 16 + kg * 8;        // ulonglong2 index within a batch row

    for (int t = 0; t < T_DIM; ++t) {
        const size_t base_t = (size_t)t * (B_DIM * D_DIM);

        // Prefetch finalization operands (independent of the matvec)
        float wx = 0.0f, hp = 0.0f;
        if (tid < 128) {
            wx = g_wx[base_t + fcol];
            hp = __ldcg(hbuf + base_t + fcol);
        }

        // Stage h[t] bgroup slice: 8192 floats = 2048 float4, 512 threads x 4
        {
            const float4* src = (const float4*)(hbuf + base_t + (size_t)bgroup * 8 * D_DIM);
            float4*       dst = (float4*)sh;
#pragma unroll
            for (int i = 0; i < 4; i++)
                dst[tid + i * 512] = __ldcg(src + tid + i * 512);
        }
        __syncthreads();

        // Matvec: acc2[b] accumulates packed (even-k, odd-k) partial sums
        ull acc2[8];
#pragma unroll
        for (int b = 0; b < 8; b++) acc2[b] = 0ull;

        const ulonglong2* shp = (const ulonglong2*)sh;
#pragma unroll
        for (int b = 0; b < 8; b++) {
            const ulonglong2* row = shp + b * 256 + koff;
#pragma unroll
            for (int q = 0; q < 8; q++) {
                ulonglong2 h2 = row[q];       // lanes vary only by kg -> 16-way bcast
                acc2[b] = fma2(h2.x, wp[2 * q],     acc2[b]);
                acc2[b] = fma2(h2.y, wp[2 * q + 1], acc2[b]);
            }
        }

        // Reduce: packed halves, then kg pair via shuffle
        float accs[8];
#pragma unroll
        for (int b = 0; b < 8; b++) {
            float lo, hi;
            unpack2(acc2[b], lo, hi);
            float s = lo + hi;
            s += __shfl_xor_sync(0xffffffffu, s, 1);
            accs[b] = s;
        }
        if (kg == 0) {
#pragma unroll
            for (int b = 0; b < 8; b++)
                red[w][e_local * 8 + b] = accs[b];
        }
        __syncthreads();

        // Final: sum 16 warps' partials, activation, stores
        if (tid < 128) {
            float s = 0.0f;
#pragma unroll
            for (int ww = 0; ww < 16; ww++) s += red[ww][tid];
            float pre = s + wx;
            float hn  = hp + alpha * tanhf(pre);
            hbuf[base_t + (size_t)B_DIM * D_DIM + fcol] = hn;     // h[t+1]
            float sig = 1.0f / (1.0f + __expf(-hn));
            outs[base_t + fcol] = hn * hn * sig;                  // h * silu(h)
        }

        grid_barrier_half(bgroup);   // publishes h[t+1] to this batch group
    }
}

// ---------------------------------------------------------------------------
// Launch wrapper
// Inputs (metadata order): x, h0, W_x, W_h, b, log_alpha
// Output layout: outs [T,B,D] then h [T+1,B,D]  (reference returns (outs, h))
// ---------------------------------------------------------------------------
extern "C" void kernel_launch(void* const* d_in, const int* in_sizes, int n_in,
                              void* d_out, int out_size)
{
    const float* x    = (const float*)d_in[0];
    const float* h0   = (const float*)d_in[1];
    const float* W_x  = (const float*)d_in[2];
    const float* W_h  = (const float*)d_in[3];
    const float* bias = (const float*)d_in[4];
    const float* la   = (const float*)d_in[5];

    float* outs = (float*)d_out;
    float* hbuf = outs + (size_t)T_DIM * B_DIM * D_DIM;

    // Phase A: input projection GEMM into g_wx
    dim3 ggrid(D_DIM / BN, (T_DIM * B_DIM) / BM);   // (8, 256)
    gemm_xwx_kernel<<<ggrid, 256>>>(x, W_x, bias);

    // h[0] = h0
    copy_h0_kernel<<<(B_DIM * D_DIM + 255) / 256, 256>>>(h0, hbuf);

    // Phase B: persistent scan
    scan_kernel<<<NC, 512>>>(W_h, la, outs, hbuf);
}

// round 8
// speedup vs baseline: 1.3402x; 1.3402x over previous
#include <cuda_runtime.h>
#include <cstdint>

// Problem constants
#define T_DIM 2048
#define B_DIM 16
#define D_DIM 1024

#define NC   128            // persistent CTAs (all co-resident; 128 < 148 SMs)
#define NCG  32             // CTAs per batch-group barrier (4 groups x 32)
#define EPC  32             // features per CTA
#define BPC  4              // batches per CTA

typedef unsigned long long ull;

// ---------------------------------------------------------------------------
// Packed fp32x2 helpers (sm_100+; IEEE-identical per lane to scalar FFMA)
// ---------------------------------------------------------------------------
__device__ __forceinline__ ull fma2(ull a, ull b, ull c) {
    ull d;
    asm("fma.rn.f32x2 %0, %1, %2, %3;" : "=l"(d) : "l"(a), "l"(b), "l"(c));
    return d;
}
__device__ __forceinline__ ull pack2(float lo, float hi) {
    ull d;
    asm("mov.b64 %0, {%1, %2};" : "=l"(d) : "f"(lo), "f"(hi));
    return d;
}
__device__ __forceinline__ void unpack2(ull v, float& lo, float& hi) {
    asm("mov.b64 {%0, %1}, %2;" : "=f"(lo), "=f"(hi) : "l"(v));
}

// ---------------------------------------------------------------------------
// GPU-scope acquire/release primitives (cheap L2 path; NOT sys-scope volatile)
// ---------------------------------------------------------------------------
__device__ __forceinline__ unsigned atom_add_acqrel(unsigned* p, unsigned v) {
    unsigned r;
    asm volatile("atom.global.add.acq_rel.gpu.u32 %0, [%1], %2;"
                 : "=r"(r) : "l"(p), "r"(v) : "memory");
    return r;
}
__device__ __forceinline__ unsigned ld_acquire(unsigned* p) {
    unsigned r;
    asm volatile("ld.global.acquire.gpu.u32 %0, [%1];" : "=r"(r) : "l"(p) : "memory");
    return r;
}
__device__ __forceinline__ unsigned ld_relaxed(unsigned* p) {
    unsigned r;
    asm volatile("ld.global.relaxed.gpu.u32 %0, [%1];" : "=r"(r) : "l"(p) : "memory");
    return r;
}
__device__ __forceinline__ void st_relaxed(unsigned* p, unsigned v) {
    asm volatile("st.global.relaxed.gpu.u32 [%0], %1;" :: "l"(p), "r"(v) : "memory");
}

// ---------------------------------------------------------------------------
// Device-global scratch (allocation-free rule). Alignment is load-bearing
// for 128-bit accesses (sm_103a wide-operand trap).
// ---------------------------------------------------------------------------
__device__ __align__(256) float g_wx[(size_t)T_DIM * B_DIM * D_DIM];  // x@W_x^T + b
__device__ unsigned g_bar_count[4];   // one barrier per batch group
__device__ unsigned g_bar_gen[4];

// ---------------------------------------------------------------------------
// 32-CTA batch-group barrier. Arrival: one acq_rel atomic per CTA (after
// bar.sync, so it releases the whole CTA's prior stores and acquires all
// earlier arrivals). Release: gen bump (acq_rel -> carries everything).
// Waiters: acquire-poll gen (plain L2 reads, no atomic-ALU serialization).
// count returns to 0 each use; gen monotonic, compared relatively ->
// graph-replay clean. Cooperative-groups grid.sync pattern; no separate
// __threadfence needed.
// ---------------------------------------------------------------------------
__device__ __forceinline__ void grid_barrier_grp(int grp) {
    __syncthreads();
    if (threadIdx.x == 0) {
        unsigned snap = ld_relaxed(&g_bar_gen[grp]);   // stable: release needs OUR arrival
        unsigned prev = atom_add_acqrel(&g_bar_count[grp], 1u);
        if (prev == NCG - 1) {
            st_relaxed(&g_bar_count[grp], 0u);         // ordered before release below
            atom_add_acqrel(&g_bar_gen[grp], 1u);      // release
        } else {
            while (ld_acquire(&g_bar_gen[grp]) == snap) { }
        }
    }
    __syncthreads();
}

// ---------------------------------------------------------------------------
// Phase A: Wx[t,b,e] = sum_d x[t,b,d] * W_x[e,d] + bias[e]
// C[M=32768, N=1024] = X * W^T, 128x128 block, 8x8 thread tile, BK=8,
// 256 threads, fp32x2 packed FMA, 2-stage SMEM double buffer (one sync/iter:
// the STS target buffer's previous readers finished before the prior sync).
// ---------------------------------------------------------------------------
#define BM 128
#define BN 128
#define BK 8

__global__ void __launch_bounds__(256, 2) gemm_xwx_kernel(
    const float* __restrict__ X, const float* __restrict__ W,
    const float* __restrict__ bias)
{
    __shared__ __align__(16) float As[2][BK][BM];   // 2 x 4KB
    __shared__ __align__(16) float Bs[2][BK][BN];   // 2 x 4KB

    const int bm  = blockIdx.y * BM;
    const int bn  = blockIdx.x * BN;
    const int tid = threadIdx.x;

    const int lrow = tid >> 1;          // 128 rows x 2 threads (4 k each as float4)
    const int lk4  = (tid & 1) * 4;

    const int trow = (tid >> 4) * 8;    // 16x16 thread grid, 8x8 outputs each
    const int tcol = (tid & 15) * 8;

    ull acc2[8][4];
#pragma unroll
    for (int i = 0; i < 8; i++)
#pragma unroll
        for (int j = 0; j < 4; j++) acc2[i][j] = 0ull;

    const float* xrow = X + (size_t)(bm + lrow) * D_DIM + lk4;
    const float* wrow = W + (size_t)(bn + lrow) * D_DIM + lk4;

    // Prologue: stage chunk 0 into buffer 0
    {
        float4 a4 = *(const float4*)(xrow);
        float4 b4 = *(const float4*)(wrow);
        As[0][lk4 + 0][lrow] = a4.x; As[0][lk4 + 1][lrow] = a4.y;
        As[0][lk4 + 2][lrow] = a4.z; As[0][lk4 + 3][lrow] = a4.w;
        Bs[0][lk4 + 0][lrow] = b4.x; Bs[0][lk4 + 1][lrow] = b4.y;
        Bs[0][lk4 + 2][lrow] = b4.z; Bs[0][lk4 + 3][lrow] = b4.w;
    }
    __syncthreads();

    int cur = 0;
    for (int k0 = 0; k0 < D_DIM; k0 += BK) {
        // Issue next chunk's global loads early (latency hidden by compute)
        float4 a4n, b4n;
        const bool have_next = (k0 + BK) < D_DIM;
        if (have_next) {
            a4n = *(const float4*)(xrow + k0 + BK);
            b4n = *(const float4*)(wrow + k0 + BK);
        }

        // Compute on current buffer
#pragma unroll
        for (int k = 0; k < BK; k++) {
            float4 ra0 = *(const float4*)&As[cur][k][trow];
            float4 ra1 = *(const float4*)&As[cur][k][trow + 4];
            ulonglong2 rb01 = *(const ulonglong2*)&Bs[cur][k][tcol];
            ulonglong2 rb23 = *(const ulonglong2*)&Bs[cur][k][tcol + 4];
            float ra[8] = {ra0.x, ra0.y, ra0.z, ra0.w, ra1.x, ra1.y, ra1.z, ra1.w};
#pragma unroll
            for (int i = 0; i < 8; i++) {
                ull aa = pack2(ra[i], ra[i]);
                acc2[i][0] = fma2(aa, rb01.x, acc2[i][0]);
                acc2[i][1] = fma2(aa, rb01.y, acc2[i][1]);
                acc2[i][2] = fma2(aa, rb23.x, acc2[i][2]);
                acc2[i][3] = fma2(aa, rb23.y, acc2[i][3]);
            }
        }

        // Stage next chunk into the other buffer (no one reads it now)
        if (have_next) {
            int nxt = cur ^ 1;
            As[nxt][lk4 + 0][lrow] = a4n.x; As[nxt][lk4 + 1][lrow] = a4n.y;
            As[nxt][lk4 + 2][lrow] = a4n.z; As[nxt][lk4 + 3][lrow] = a4n.w;
            Bs[nxt][lk4 + 0][lrow] = b4n.x; Bs[nxt][lk4 + 1][lrow] = b4n.y;
            Bs[nxt][lk4 + 2][lrow] = b4n.z; Bs[nxt][lk4 + 3][lrow] = b4n.w;
        }
        __syncthreads();
        cur ^= 1;
    }

    // Epilogue: unpack, add bias, store
#pragma unroll
    for (int i = 0; i < 8; i++) {
        float c[8];
#pragma unroll
        for (int jp = 0; jp < 4; jp++) unpack2(acc2[i][jp], c[2 * jp], c[2 * jp + 1]);
        float* crow = g_wx + (size_t)(bm + trow + i) * D_DIM + bn + tcol;
#pragma unroll
        for (int j = 0; j < 8; j += 4) {
            float4 v;
            v.x = c[j + 0] + bias[bn + tcol + j + 0];
            v.y = c[j + 1] + bias[bn + tcol + j + 1];
            v.z = c[j + 2] + bias[bn + tcol + j + 2];
            v.w = c[j + 3] + bias[bn + tcol + j + 3];
            *(float4*)(crow + j) = v;
        }
    }
}

// ---------------------------------------------------------------------------
// Copy h0 into the h-history buffer at t=0
// ---------------------------------------------------------------------------
__global__ void copy_h0_kernel(const float* __restrict__ h0, float* __restrict__ hbuf)
{
    int i = blockIdx.x * blockDim.x + threadIdx.x;
    if (i < B_DIM * D_DIM) hbuf[i] = h0[i];
}

// ---------------------------------------------------------------------------
// Phase B: persistent scan.
// Grid = 128 CTAs = 4 bgroups (4 batches each) x 32 egroups (32 features).
// Batch groups fully independent -> 4 separate 32-CTA barriers.
// W_h slice in REGISTERS: warp w owns k in [64w, 64w+64), lane = e_local
// (0..31) -> thread holds W[e0+lane, 64w..64w+63] = 32 packed pairs (64 regs).
// Per step: stage h[t] bgroup slice (16KB) -> SMEM; matvec with full-warp
// broadcast LDS + packed fp32x2 FMA (4 indep chains; fma-pipe-bound at
// ~1024 cyc/SM); SMEM cross-warp reduce; 128 threads finalize with h_prev
// carried in REGISTERS (coalesced stores); rotating g_wx prefetch.
// ---------------------------------------------------------------------------
__global__ void __launch_bounds__(512, 1) scan_kernel(
    const float* __restrict__ Wh, const float* __restrict__ log_alpha_ptr,
    float* __restrict__ outs, float* __restrict__ hbuf)
{
    __shared__ __align__(16) float sh[BPC * D_DIM];          // 16 KB: h[t], 4 batches
    __shared__ __align__(16) float red[16][BPC * EPC + 4];   // cross-warp partials

    const int tid    = threadIdx.x;
    const int w      = tid >> 5;             // warp id: k-range [64w, 64w+64)
    const int lane   = tid & 31;             // e_local
    const int bgroup = blockIdx.x & 3;       // batches [bgroup*4, bgroup*4+4)
    const int e0     = (blockIdx.x >> 2) * EPC;

    // --- W_h slice into registers (once) ---
    ull wp[32];                               // 64 floats = 16 float4
    {
        const float4* wrow = (const float4*)(Wh + (size_t)(e0 + lane) * D_DIM + w * 64);
#pragma unroll
        for (int q = 0; q < 16; q++) {
            float4 v = wrow[q];
            wp[2 * q]     = pack2(v.x, v.y);
            wp[2 * q + 1] = pack2(v.z, v.w);
        }
    }
    const float alpha = expf(log_alpha_ptr[0]);

    // Finalization ids (tid < 128): tid = fb*32 + fe -> coalesced 128B rows
    const int    fb   = tid >> 5;            // 0..3
    const int    fe   = tid & 31;            // 0..31
    const size_t fcol = (size_t)(bgroup * BPC + fb) * D_DIM + e0 + fe;

    // h_prev carried in a register; g_wx rotating prefetch
    float hp = 0.0f, wx = 0.0f;
    if (tid < 128) {
        hp = hbuf[fcol];                     // h0 (copy kernel completed)
        wx = g_wx[fcol];                     // step 0 operand
    }

    const float4* stage_src0 = (const float4*)(hbuf + (size_t)bgroup * BPC * D_DIM);

    for (int t = 0; t < T_DIM; ++t) {
        const size_t base_t = (size_t)t * (B_DIM * D_DIM);

        // Stage h[t] bgroup slice: 4096 floats = 1024 float4 (2 per thread)
        {
            const float4* src = stage_src0 + (base_t >> 2);
            float4*       dst = (float4*)sh;
            dst[tid]       = __ldcg(src + tid);
            dst[tid + 512] = __ldcg(src + tid + 512);
        }
        __syncthreads();

        // Matvec: 4 independent packed accumulator chains (one per batch)
        ull a0 = 0ull, a1 = 0ull, a2 = 0ull, a3 = 0ull;
        const ulonglong2* r0 = (const ulonglong2*)(sh + 0 * D_DIM + w * 64);
        const ulonglong2* r1 = (const ulonglong2*)(sh + 1 * D_DIM + w * 64);
        const ulonglong2* r2 = (const ulonglong2*)(sh + 2 * D_DIM + w * 64);
        const ulonglong2* r3 = (const ulonglong2*)(sh + 3 * D_DIM + w * 64);
#pragma unroll
        for (int j = 0; j < 16; j++) {
            ulonglong2 h0v = r0[j];          // all lanes same addr -> broadcast
            ulonglong2 h1v = r1[j];
            ulonglong2 h2v = r2[j];
            ulonglong2 h3v = r3[j];
            ull wlo = wp[2 * j], whi = wp[2 * j + 1];
            a0 = fma2(h0v.x, wlo, a0);  a0 = fma2(h0v.y, whi, a0);
            a1 = fma2(h1v.x, wlo, a1);  a1 = fma2(h1v.y, whi, a1);
            a2 = fma2(h2v.x, wlo, a2);  a2 = fma2(h2v.y, whi, a2);
            a3 = fma2(h3v.x, wlo, a3);  a3 = fma2(h3v.y, whi, a3);
        }

        // Collapse packed halves; store per-warp partials (conflict-free)
        {
            float lo, hi;
            unpack2(a0, lo, hi); red[w][0 * EPC + lane] = lo + hi;
            unpack2(a1, lo, hi); red[w][1 * EPC + lane] = lo + hi;
            unpack2(a2, lo, hi); red[w][2 * EPC + lane] = lo + hi;
            unpack2(a3, lo, hi); red[w][3 * EPC + lane] = lo + hi;
        }
        __syncthreads();

        // Finalize: sum 16 warps' partials, activation, coalesced stores
        float wx_next = 0.0f;
        if (tid < 128) {
            float s = 0.0f;
#pragma unroll
            for (int ww = 0; ww < 16; ww++) s += red[ww][tid];
            float pre = s + wx;
            float hn  = hp + alpha * tanhf(pre);
            hbuf[base_t + (size_t)B_DIM * D_DIM + fcol] = hn;     // h[t+1]
            float sig = 1.0f / (1.0f + __expf(-hn));
            outs[base_t + fcol] = hn * hn * sig;                  // h * silu(h)
            hp = hn;                                              // carry in register
            if (t + 1 < T_DIM)
                wx_next = g_wx[base_t + (size_t)B_DIM * D_DIM + fcol]; // prefetch
        }
        wx = wx_next;

        if (t + 1 < T_DIM)
            grid_barrier_grp(bgroup);    // release chain publishes h[t+1]
    }
}

// ---------------------------------------------------------------------------
// Launch wrapper
// Inputs (metadata order): x, h0, W_x, W_h, b, log_alpha
// Output layout: outs [T,B,D] then h [T+1,B,D]
// ---------------------------------------------------------------------------
extern "C" void kernel_launch(void* const* d_in, const int* in_sizes, int n_in,
                              void* d_out, int out_size)
{
    const float* x    = (const float*)d_in[0];
    const float* h0   = (const float*)d_in[1];
    const float* W_x  = (const float*)d_in[2];
    const float* W_h  = (const float*)d_in[3];
    const float* bias = (const float*)d_in[4];
    const float* la   = (const float*)d_in[5];

    float* outs = (float*)d_out;
    float* hbuf = outs + (size_t)T_DIM * B_DIM * D_DIM;

    dim3 ggrid(D_DIM / BN, (T_DIM * B_DIM) / BM);   // (8, 256)
    gemm_xwx_kernel<<<ggrid, 256>>>(x, W_x, bias);

    copy_h0_kernel<<<(B_DIM * D_DIM + 255) / 256, 256>>>(h0, hbuf);

    scan_kernel<<<NC, 512>>>(W_h, la, outs, hbuf);
}

// round 12
// speedup vs baseline: 1.6343x; 1.2195x over previous
#include <cuda_runtime.h>
#include <cstdint>

// Problem constants
#define T_DIM 2048
#define B_DIM 16
#define D_DIM 1024

#define NC   128            // persistent CTAs (all co-resident; 128 < 148 SMs)
#define NCG  32             // CTAs per batch-group barrier (4 groups x 32)
#define EPC  32             // features per CTA
#define BPC  4              // batches per CTA

typedef unsigned long long ull;

// ---------------------------------------------------------------------------
// Packed fp32x2 helpers (sm_100+; IEEE-identical per lane to scalar FFMA)
// ---------------------------------------------------------------------------
__device__ __forceinline__ ull fma2(ull a, ull b, ull c) {
    ull d;
    asm("fma.rn.f32x2 %0, %1, %2, %3;" : "=l"(d) : "l"(a), "l"(b), "l"(c));
    return d;
}
__device__ __forceinline__ ull pack2(float lo, float hi) {
    ull d;
    asm("mov.b64 %0, {%1, %2};" : "=l"(d) : "f"(lo), "f"(hi));
    return d;
}
__device__ __forceinline__ void unpack2(ull v, float& lo, float& hi) {
    asm("mov.b64 {%0, %1}, %2;" : "=f"(lo), "=f"(hi) : "l"(v));
}

// ---------------------------------------------------------------------------
// GPU-scope release/acquire primitives (L2 path)
// ---------------------------------------------------------------------------
__device__ __forceinline__ void st_release(unsigned* p, unsigned v) {
    asm volatile("st.global.release.gpu.u32 [%0], %1;" :: "l"(p), "r"(v) : "memory");
}
__device__ __forceinline__ unsigned ld_acquire(unsigned* p) {
    unsigned r;
    asm volatile("ld.global.acquire.gpu.u32 %0, [%1];" : "=r"(r) : "l"(p) : "memory");
    return r;
}
__device__ __forceinline__ unsigned ld_relaxed(unsigned* p) {
    unsigned r;
    asm volatile("ld.global.relaxed.gpu.u32 %0, [%1];" : "=r"(r) : "l"(p) : "memory");
    return r;
}

// ---------------------------------------------------------------------------
// Device-global scratch (allocation-free rule). Alignment is load-bearing
// for 128-bit accesses (sm_103a wide-operand trap).
// Flag array: one 128B line per batch group (32 u32 slots). Never reset —
// each CTA reads its OWN slot at entry as the replay-base (self-written,
// race-free) and signals base+t+1. Monotonic across graph replays; all
// slots in a group end each replay at the same value (base+T-1).
// ---------------------------------------------------------------------------
__device__ __align__(256) float g_wx[(size_t)T_DIM * B_DIM * D_DIM];  // x@W_x^T + b
__device__ __align__(128) unsigned g_flags[4 * NCG];

// ---------------------------------------------------------------------------
// Phase A: Wx[t,b,e] = sum_d x[t,b,d] * W_x[e,d] + bias[e]
// C[M=32768, N=1024] = X * W^T, 128x128 block, 8x8 thread tile, BK=8,
// 256 threads, fp32x2 packed FMA, 2-stage SMEM double buffer.
// ---------------------------------------------------------------------------
#define BM 128
#define BN 128
#define BK 8

__global__ void __launch_bounds__(256, 2) gemm_xwx_kernel(
    const float* __restrict__ X, const float* __restrict__ W,
    const float* __restrict__ bias)
{
    __shared__ __align__(16) float As[2][BK][BM];   // 2 x 4KB
    __shared__ __align__(16) float Bs[2][BK][BN];   // 2 x 4KB

    const int bm  = blockIdx.y * BM;
    const int bn  = blockIdx.x * BN;
    const int tid = threadIdx.x;

    const int lrow = tid >> 1;
    const int lk4  = (tid & 1) * 4;

    const int trow = (tid >> 4) * 8;
    const int tcol = (tid & 15) * 8;

    ull acc2[8][4];
#pragma unroll
    for (int i = 0; i < 8; i++)
#pragma unroll
        for (int j = 0; j < 4; j++) acc2[i][j] = 0ull;

    const float* xrow = X + (size_t)(bm + lrow) * D_DIM + lk4;
    const float* wrow = W + (size_t)(bn + lrow) * D_DIM + lk4;

    // Prologue: stage chunk 0 into buffer 0
    {
        float4 a4 = *(const float4*)(xrow);
        float4 b4 = *(const float4*)(wrow);
        As[0][lk4 + 0][lrow] = a4.x; As[0][lk4 + 1][lrow] = a4.y;
        As[0][lk4 + 2][lrow] = a4.z; As[0][lk4 + 3][lrow] = a4.w;
        Bs[0][lk4 + 0][lrow] = b4.x; Bs[0][lk4 + 1][lrow] = b4.y;
        Bs[0][lk4 + 2][lrow] = b4.z; Bs[0][lk4 + 3][lrow] = b4.w;
    }
    __syncthreads();

    int cur = 0;
    for (int k0 = 0; k0 < D_DIM; k0 += BK) {
        float4 a4n, b4n;
        const bool have_next = (k0 + BK) < D_DIM;
        if (have_next) {
            a4n = *(const float4*)(xrow + k0 + BK);
            b4n = *(const float4*)(wrow + k0 + BK);
        }

#pragma unroll
        for (int k = 0; k < BK; k++) {
            float4 ra0 = *(const float4*)&As[cur][k][trow];
            float4 ra1 = *(const float4*)&As[cur][k][trow + 4];
            ulonglong2 rb01 = *(const ulonglong2*)&Bs[cur][k][tcol];
            ulonglong2 rb23 = *(const ulonglong2*)&Bs[cur][k][tcol + 4];
            float ra[8] = {ra0.x, ra0.y, ra0.z, ra0.w, ra1.x, ra1.y, ra1.z, ra1.w};
#pragma unroll
            for (int i = 0; i < 8; i++) {
                ull aa = pack2(ra[i], ra[i]);
                acc2[i][0] = fma2(aa, rb01.x, acc2[i][0]);
                acc2[i][1] = fma2(aa, rb01.y, acc2[i][1]);
                acc2[i][2] = fma2(aa, rb23.x, acc2[i][2]);
                acc2[i][3] = fma2(aa, rb23.y, acc2[i][3]);
            }
        }

        if (have_next) {
            int nxt = cur ^ 1;
            As[nxt][lk4 + 0][lrow] = a4n.x; As[nxt][lk4 + 1][lrow] = a4n.y;
            As[nxt][lk4 + 2][lrow] = a4n.z; As[nxt][lk4 + 3][lrow] = a4n.w;
            Bs[nxt][lk4 + 0][lrow] = b4n.x; Bs[nxt][lk4 + 1][lrow] = b4n.y;
            Bs[nxt][lk4 + 2][lrow] = b4n.z; Bs[nxt][lk4 + 3][lrow] = b4n.w;
        }
        __syncthreads();
        cur ^= 1;
    }

#pragma unroll
    for (int i = 0; i < 8; i++) {
        float c[8];
#pragma unroll
        for (int jp = 0; jp < 4; jp++) unpack2(acc2[i][jp], c[2 * jp], c[2 * jp + 1]);
        float* crow = g_wx + (size_t)(bm + trow + i) * D_DIM + bn + tcol;
#pragma unroll
        for (int j = 0; j < 8; j += 4) {
            float4 v;
            v.x = c[j + 0] + bias[bn + tcol + j + 0];
            v.y = c[j + 1] + bias[bn + tcol + j + 1];
            v.z = c[j + 2] + bias[bn + tcol + j + 2];
            v.w = c[j + 3] + bias[bn + tcol + j + 3];
            *(float4*)(crow + j) = v;
        }
    }
}

// ---------------------------------------------------------------------------
// Copy h0 into the h-history buffer at t=0
// ---------------------------------------------------------------------------
__global__ void copy_h0_kernel(const float* __restrict__ h0, float* __restrict__ hbuf)
{
    int i = blockIdx.x * blockDim.x + threadIdx.x;
    if (i < B_DIM * D_DIM) hbuf[i] = h0[i];
}

// ---------------------------------------------------------------------------
// Phase B: persistent scan.
// Grid = 128 CTAs = 4 bgroups (4 batches each) x 32 egroups (32 features).
// Sync per bgroup via a FLAG-ARRAY barrier: each CTA st.release's its own
// slot (no atomic serialization, no leader release hop); warp 0's 32 lanes
// acquire-poll the group's single 128B flag line. Critical path per step:
// h[t+1] STG -> bar.sync 1,128 (finalize warps only) -> flag release ->
// peers observe -> stage -> matvec. silu/outs store + g_wx DRAM prefetch
// ride AFTER the release, off the recurrence path.
// ---------------------------------------------------------------------------
__global__ void __launch_bounds__(512, 1) scan_kernel(
    const float* __restrict__ Wh, const float* __restrict__ log_alpha_ptr,
    float* __restrict__ outs, float* __restrict__ hbuf)
{
    __shared__ __align__(16) float sh[BPC * D_DIM];          // 16 KB: h[t], 4 batches
    __shared__ __align__(16) float red[16][BPC * EPC + 4];   // cross-warp partials
    __shared__ unsigned s_base;

    const int tid    = threadIdx.x;
    const int w      = tid >> 5;             // warp id: k-range [64w, 64w+64)
    const int lane   = tid & 31;             // e_local
    const int bgroup = blockIdx.x & 3;       // batches [bgroup*4, bgroup*4+4)
    const int egrp   = blockIdx.x >> 2;      // 0..31 = slot in the flag line
    const int e0     = egrp * EPC;

    unsigned* const flag_line = g_flags + bgroup * NCG;

    // Replay base: my own slot's current value (self-written only -> race-free)
    if (tid == 0) s_base = ld_relaxed(flag_line + egrp);

    // --- W_h slice into registers (once) ---
    ull wp[32];                               // 64 floats = 16 float4
    {
        const float4* wrow = (const float4*)(Wh + (size_t)(e0 + lane) * D_DIM + w * 64);
#pragma unroll
        for (int q = 0; q < 16; q++) {
            float4 v = wrow[q];
            wp[2 * q]     = pack2(v.x, v.y);
            wp[2 * q + 1] = pack2(v.z, v.w);
        }
    }
    const float alpha = expf(log_alpha_ptr[0]);

    // Finalization ids (tid < 128): tid = fb*32 + fe -> coalesced 128B rows
    const int    fb   = tid >> 5;            // 0..3
    const int    fe   = tid & 31;            // 0..31
    const size_t fcol = (size_t)(bgroup * BPC + fb) * D_DIM + e0 + fe;

    // h_prev carried in a register; g_wx rotating prefetch
    float hp = 0.0f, wx = 0.0f;
    if (tid < 128) {
        hp = hbuf[fcol];                     // h0 (copy kernel completed)
        wx = g_wx[fcol];                     // step 0 operand
    }
    __syncthreads();                          // publish s_base
    const unsigned base = s_base;

    const float4* stage_src0 = (const float4*)(hbuf + (size_t)bgroup * BPC * D_DIM);

    for (int t = 0; t < T_DIM; ++t) {
        const size_t base_t = (size_t)t * (B_DIM * D_DIM);

        // Stage h[t] bgroup slice: 4096 floats = 1024 float4 (2 per thread)
        {
            const float4* src = stage_src0 + (base_t >> 2);
            float4*       dst = (float4*)sh;
            dst[tid]       = __ldcg(src + tid);
            dst[tid + 512] = __ldcg(src + tid + 512);
        }
        __syncthreads();

        // Matvec: 4 independent packed accumulator chains (one per batch)
        ull a0 = 0ull, a1 = 0ull, a2 = 0ull, a3 = 0ull;
        const ulonglong2* r0 = (const ulonglong2*)(sh + 0 * D_DIM + w * 64);
        const ulonglong2* r1 = (const ulonglong2*)(sh + 1 * D_DIM + w * 64);
        const ulonglong2* r2 = (const ulonglong2*)(sh + 2 * D_DIM + w * 64);
        const ulonglong2* r3 = (const ulonglong2*)(sh + 3 * D_DIM + w * 64);
#pragma unroll
        for (int j = 0; j < 16; j++) {
            ulonglong2 h0v = r0[j];          // all lanes same addr -> broadcast
            ulonglong2 h1v = r1[j];
            ulonglong2 h2v = r2[j];
            ulonglong2 h3v = r3[j];
            ull wlo = wp[2 * j], whi = wp[2 * j + 1];
            a0 = fma2(h0v.x, wlo, a0);  a0 = fma2(h0v.y, whi, a0);
            a1 = fma2(h1v.x, wlo, a1);  a1 = fma2(h1v.y, whi, a1);
            a2 = fma2(h2v.x, wlo, a2);  a2 = fma2(h2v.y, whi, a2);
            a3 = fma2(h3v.x, wlo, a3);  a3 = fma2(h3v.y, whi, a3);
        }

        // Collapse packed halves; store per-warp partials (conflict-free)
        {
            float lo, hi;
            unpack2(a0, lo, hi); red[w][0 * EPC + lane] = lo + hi;
            unpack2(a1, lo, hi); red[w][1 * EPC + lane] = lo + hi;
            unpack2(a2, lo, hi); red[w][2 * EPC + lane] = lo + hi;
            unpack2(a3, lo, hi); red[w][3 * EPC + lane] = lo + hi;
        }
        __syncthreads();

        // Finalize (warps 0-3): reduce, recurrence, h store, release; then
        // the off-critical-path tail (silu/outs, g_wx prefetch).
        if (tid < 128) {
            float s = 0.0f;
#pragma unroll
            for (int ww = 0; ww < 16; ww++) s += red[ww][tid];
            float pre = s + wx;
            float hn  = hp + alpha * tanhf(pre);
            hbuf[base_t + (size_t)B_DIM * D_DIM + fcol] = hn;     // h[t+1]
            hp = hn;

            if (t + 1 < T_DIM) {
                asm volatile("bar.sync 1, 128;" ::: "memory");    // h stores done (128 thr)
                if (tid == 0)
                    st_release(flag_line + egrp, base + (unsigned)(t + 1));
            }

            // Off critical path:
            float sig = 1.0f / (1.0f + __expf(-hn));
            outs[base_t + fcol] = hn * hn * sig;                  // h * silu(h)
            wx = (t + 1 < T_DIM)
                   ? g_wx[base_t + (size_t)B_DIM * D_DIM + fcol]  // DRAM prefetch
                   : 0.0f;
        }

        // Wait for all 32 CTAs of this group to have published h[t+1]
        if (t + 1 < T_DIM) {
            if (tid < 32) {
                const unsigned tgt = base + (unsigned)(t + 1);
                unsigned* fp = flag_line + tid;
                while (true) {
                    unsigned v = ld_acquire(fp);
                    if (__all_sync(0xffffffffu, v >= tgt)) break;
                }
            }
            __syncthreads();
        }
    }
}

// ---------------------------------------------------------------------------
// Launch wrapper
// Inputs (metadata order): x, h0, W_x, W_h, b, log_alpha
// Output layout: outs [T,B,D] then h [T+1,B,D]
// ---------------------------------------------------------------------------
extern "C" void kernel_launch(void* const* d_in, const int* in_sizes, int n_in,
                              void* d_out, int out_size)
{
    const float* x    = (const float*)d_in[0];
    const float* h0   = (const float*)d_in[1];
    const float* W_x  = (const float*)d_in[2];
    const float* W_h  = (const float*)d_in[3];
    const float* bias = (const float*)d_in[4];
    const float* la   = (const float*)d_in[5];

    float* outs = (float*)d_out;
    float* hbuf = outs + (size_t)T_DIM * B_DIM * D_DIM;

    dim3 ggrid(D_DIM / BN, (T_DIM * B_DIM) / BM);   // (8, 256)
    gemm_xwx_kernel<<<ggrid, 256>>>(x, W_x, bias);

    copy_h0_kernel<<<(B_DIM * D_DIM + 255) / 256, 256>>>(h0, hbuf);

    scan_kernel<<<NC, 512>>>(W_h, la, outs, hbuf);
}